// round 6
// baseline (speedup 1.0000x reference)
#include <cuda_runtime.h>
#include <cuda_fp16.h>
#include <cstdint>

#define N_DIM 384
#define S_DIM 64
#define C_IN  64
#define C_H   32
#define C_OUT 128
#define LN_EPS 1e-5f

// ---------------- device scratch ----------------
__device__ __half g_A[N_DIM * C_H * S_DIM];      // [n][c][s] fp16
__device__ __half g_B[N_DIM * C_H * S_DIM];      // [n][d][s] fp16
__device__ __half g_W[16 * C_OUT * 64];          // [cidx][o][kk] fp16
__device__ unsigned long long g_mbits[N_DIM];

#define SWZ(b) ((b) ^ (((b) >> 3) & 0x70))

__device__ __forceinline__ uint32_t smem_u32(const void* p) {
    uint32_t a;
    asm("{ .reg .u64 t; cvta.to.shared.u64 t, %1; cvt.u32.u64 %0, t; }" : "=r"(a) : "l"(p));
    return a;
}
__device__ __forceinline__ void ldsm4(uint32_t r[4], uint32_t a) {
    asm volatile("ldmatrix.sync.aligned.m8n8.x4.shared.b16 {%0,%1,%2,%3}, [%4];"
                 : "=r"(r[0]), "=r"(r[1]), "=r"(r[2]), "=r"(r[3]) : "r"(a));
}
__device__ __forceinline__ void mma16816(float c[4], const uint32_t a[4], const uint32_t b[2]) {
    asm volatile("mma.sync.aligned.m16n8k16.row.col.f32.f16.f16.f32 "
                 "{%0,%1,%2,%3}, {%4,%5,%6,%7}, {%8,%9}, {%0,%1,%2,%3};"
                 : "+f"(c[0]), "+f"(c[1]), "+f"(c[2]), "+f"(c[3])
                 : "r"(a[0]), "r"(a[1]), "r"(a[2]), "r"(a[3]), "r"(b[0]), "r"(b[1]));
}
#define CP16(dst, src) asm volatile("cp.async.cg.shared.global [%0], [%1], 16;" :: "r"(dst), "l"(src))
#define CP_COMMIT()    asm volatile("cp.async.commit_group;" ::: "memory")
#define CP_WAIT(n)     asm volatile("cp.async.wait_group %0;" :: "n"(n) : "memory")

// ---------------------------------------------------------------------------
// prep: LN + dual projection + mask -> fp16 [n][ch][s]; mask bitmasks
// one block per n, 512 threads (16 warps x 4 s-iterations)
// ---------------------------------------------------------------------------
__global__ __launch_bounds__(512) void prep_kernel(
    const float* __restrict__ m, const int* __restrict__ mask,
    const float* __restrict__ gamma, const float* __restrict__ beta,
    const float* __restrict__ Wa, const float* __restrict__ Wb)
{
    __shared__ float sWaT[C_IN * C_H];
    __shared__ float sWbT[C_IN * C_H];
    __shared__ float sMn[16][C_IN];
    __shared__ float sa[C_H * 65];
    __shared__ float sb[C_H * 65];

    int tid = threadIdx.x, w = tid >> 5, l = tid & 31;
    int n = blockIdx.x;

    for (int i = tid; i < C_H * C_IN; i += 512) {
        int c = i >> 6, k = i & 63;
        sWaT[k * C_H + c] = Wa[i];
        sWbT[k * C_H + c] = Wb[i];
    }
    __syncthreads();

    float gam0 = gamma[l], gam1 = gamma[l + 32];
    float bet0 = beta[l],  bet1 = beta[l + 32];

    for (int it = 0; it < 4; it++) {
        int s = it * 16 + w;
        int row = s * N_DIM + n;
        const float* mp = m + (size_t)row * C_IN;
        float v0 = mp[l], v1 = mp[l + 32];
        float sum = v0 + v1;
        #pragma unroll
        for (int o = 16; o; o >>= 1) sum += __shfl_xor_sync(0xffffffffu, sum, o);
        float mu = sum * (1.f / 64.f);
        float d0 = v0 - mu, d1 = v1 - mu;
        float sq = d0 * d0 + d1 * d1;
        #pragma unroll
        for (int o = 16; o; o >>= 1) sq += __shfl_xor_sync(0xffffffffu, sq, o);
        float inv = rsqrtf(sq * (1.f / 64.f) + LN_EPS);
        sMn[w][l]      = d0 * inv * gam0 + bet0;
        sMn[w][l + 32] = d1 * inv * gam1 + bet1;
        __syncwarp();
        float mf = (float)mask[row];
        float aa = 0.f, bb = 0.f;
        #pragma unroll
        for (int k = 0; k < C_IN; k++) {
            float x = sMn[w][k];
            aa += x * sWaT[k * C_H + l];
            bb += x * sWbT[k * C_H + l];
        }
        sa[l * 65 + s] = aa * mf;
        sb[l * 65 + s] = bb * mf;
        __syncwarp();
    }
    __syncthreads();

    for (int e = tid; e < C_H * S_DIM; e += 512) {
        int c = e >> 6, s = e & 63;
        g_A[n * 2048 + e] = __float2half(sa[c * 65 + s]);
        g_B[n * 2048 + e] = __float2half(sb[c * 65 + s]);
    }

    if (w == 0) {
        unsigned b0 = __ballot_sync(0xffffffffu, mask[l * N_DIM + n] != 0);
        unsigned b1 = __ballot_sync(0xffffffffu, mask[(l + 32) * N_DIM + n] != 0);
        if (l == 0) g_mbits[n] = (unsigned long long)b0 | ((unsigned long long)b1 << 32);
    }
}

// ---------------------------------------------------------------------------
// Wo gather: g_W[cidx=sl*4+ksub][o][kk] = fp16(Wo[o][c*32+d])
//   c = sl*8 + ksub*2 + (kk>>5),  d = kk&31
// ---------------------------------------------------------------------------
__global__ __launch_bounds__(256) void wo_kernel(const float* __restrict__ Wo)
{
    __shared__ float rowv[1024];
    int o = blockIdx.x, tid = threadIdx.x;
    for (int i = tid; i < 1024; i += 256) rowv[i] = Wo[o * 1024 + i];
    __syncthreads();
    for (int r = tid; r < 1024; r += 256) {
        int cidx = r >> 6, kk = r & 63;
        int sl = cidx >> 2, ksub = cidx & 3;
        int c = sl * 8 + ksub * 2 + (kk >> 5), d = kk & 31;
        g_W[cidx * 8192 + o * 64 + kk] = __float2half(rowv[c * 32 + d]);
    }
}

// ---------------------------------------------------------------------------
// main: CTA = 8i x 8j = 64 pairs, 2 CTAs/SM.
// GEMM1 split into M-halves (each half = 4 cl = 2 ksub chunks) so Zs needs
// only 2 buffers.  smem: As 32K | Bs 32K | Zs 2x8K | Wo 2x16K | invd
// ---------------------------------------------------------------------------
#define OFF_AS 0u
#define OFF_BS 32768u
#define OFF_ZS 65536u
#define OFF_WO 81920u
#define OFF_IV 114688u
#define SMEM_BYTES (114688 + 256)

__global__ void __launch_bounds__(256, 2) main_kernel(
    const float* __restrict__ bo, float* __restrict__ out)
{
    extern __shared__ char sm[];
    const uint32_t smb = smem_u32(sm);
    const int tid = threadIdx.x, wid = tid >> 5, lane = tid & 31;
    const int i0 = blockIdx.y * 8, j0 = blockIdx.x * 8;
    float* sInvd = (float*)(sm + OFF_IV);

    if (tid < 64) {
        unsigned long long wv = g_mbits[i0 + (tid >> 3)] & g_mbits[j0 + (tid & 7)];
        sInvd[tid] = 1.f / fmaxf((float)__popcll(wv), 1.f);
    }

    // load A/B tiles (256 rows x 128B each, contiguous), swizzled
    {
        const char* srcA = (const char*)g_A + (size_t)i0 * 4096;
        const char* srcB = (const char*)g_B + (size_t)j0 * 4096;
        #pragma unroll
        for (int q = 0; q < 8; q++) {
            uint32_t rel = (uint32_t)(tid + q * 256) * 16u;
            uint32_t sw = SWZ(rel);
            *(uint4*)(sm + OFF_AS + sw) = *(const uint4*)(srcA + rel);
            *(uint4*)(sm + OFF_BS + sw) = *(const uint4*)(srcB + rel);
        }
    }

    // prefetch Wo chunk 0
    {
        const char* src = (const char*)g_W;
        #pragma unroll
        for (int q = 0; q < 4; q++) {
            uint32_t rel = (uint32_t)(tid + q * 256) * 16u;
            CP16(smb + OFF_WO + SWZ(rel), src + rel);
        }
        CP_COMMIT();
    }
    __syncthreads();

    const int wm = wid >> 2, wn = wid & 3;   // GEMM1: 2x4 warps, M16 x N64 tiles
    const int lr = lane & 15;
    const int lc = (lane >> 4) << 4;
    const int mrow = lane >> 2;
    const int ncol = (lane & 3) * 2;

    float acc2[2][4][4];
    #pragma unroll
    for (int a = 0; a < 2; a++)
        #pragma unroll
        for (int b = 0; b < 4; b++)
            #pragma unroll
            for (int c = 0; c < 4; c++) acc2[a][b][c] = 0.f;

    int cidx = 0;
    for (int sl = 0; sl < 4; sl++) {
        for (int mh = 0; mh < 2; mh++) {
            // ---- GEMM1 half: M=32 (m = cl_loc*8 + i, cl = mh*4+cl_loc), N=256, K=64
            float acc1[8][4];
            #pragma unroll
            for (int b = 0; b < 8; b++)
                #pragma unroll
                for (int c = 0; c < 4; c++) acc1[b][c] = 0.f;

            #pragma unroll
            for (int k = 0; k < 4; k++) {
                uint32_t af[4];
                {
                    int mm = wm * 16 + lr;             // 0..31 across wm
                    int i = mm & 7, cl = mh * 4 + (mm >> 3);
                    int r = i * 32 + sl * 8 + cl;      // As row
                    ldsm4(af, smb + OFF_AS + SWZ((uint32_t)(r * 128 + k * 32 + lc)));
                }
                uint32_t bf[8][2];
                #pragma unroll
                for (int tp = 0; tp < 4; tp++) {
                    uint32_t q[4];
                    int nn = wn * 64 + tp * 16 + lr;
                    ldsm4(q, smb + OFF_BS + SWZ((uint32_t)(nn * 128 + k * 32 + lc)));
                    bf[2*tp][0] = q[0]; bf[2*tp+1][0] = q[1];
                    bf[2*tp][1] = q[2]; bf[2*tp+1][1] = q[3];
                }
                #pragma unroll
                for (int tn = 0; tn < 8; tn++)
                    mma16816(acc1[tn], af, bf[tn]);
            }
            __syncthreads();   // previous GEMM2 chunk finished reading Zs

            // ---- remap this half -> Zs buffers 0/1 ----
            #pragma unroll
            for (int tn = 0; tn < 8; tn++) {
                int nn = wn * 64 + tn * 8 + ncol;
                int j = nn >> 5, d = nn & 31;
                #pragma unroll
                for (int h = 0; h < 2; h++) {
                    int mm = wm * 16 + mrow + h * 8;
                    int i = mm & 7, clq = mm >> 3;        // cl_loc 0..3
                    int pair = i * 8 + j;
                    uint32_t rel = (uint32_t)(pair * 128 + (((clq & 1) << 5) + d) * 2);
                    __half2 hv = __floats2half2_rn(acc1[tn][h*2], acc1[tn][h*2+1]);
                    *(__half2*)(sm + OFF_ZS + (uint32_t)(clq >> 1) * 8192u + SWZ(rel)) = hv;
                }
            }
            __syncthreads();

            // ---- GEMM2: 2 chunks for this half ----
            const int pb = wm * 32, ob = wn * 32;
            #pragma unroll
            for (int kq = 0; kq < 2; kq++, cidx++) {
                if (cidx + 1 < 16) {
                    const char* src = (const char*)g_W + (size_t)(cidx + 1) * 16384;
                    uint32_t dst = smb + OFF_WO + (uint32_t)((cidx + 1) & 1) * 16384u;
                    #pragma unroll
                    for (int q = 0; q < 4; q++) {
                        uint32_t rel = (uint32_t)(tid + q * 256) * 16u;
                        CP16(dst + SWZ(rel), src + rel);
                    }
                    CP_COMMIT();
                    CP_WAIT(1);
                } else {
                    CP_WAIT(0);
                }
                __syncthreads();

                uint32_t zbase = smb + OFF_ZS + (uint32_t)kq * 8192u;
                uint32_t wbase = smb + OFF_WO + (uint32_t)(cidx & 1) * 16384u;
                #pragma unroll
                for (int k = 0; k < 4; k++) {
                    uint32_t af[2][4];
                    #pragma unroll
                    for (int tm = 0; tm < 2; tm++) {
                        int p = pb + tm * 16 + lr;
                        ldsm4(af[tm], zbase + SWZ((uint32_t)(p * 128 + k * 32 + lc)));
                    }
                    uint32_t bf[4][2];
                    #pragma unroll
                    for (int tp = 0; tp < 2; tp++) {
                        uint32_t q[4];
                        int o = ob + tp * 16 + lr;
                        ldsm4(q, wbase + SWZ((uint32_t)(o * 128 + k * 32 + lc)));
                        bf[2*tp][0] = q[0]; bf[2*tp+1][0] = q[1];
                        bf[2*tp][1] = q[2]; bf[2*tp+1][1] = q[3];
                    }
                    #pragma unroll
                    for (int tm = 0; tm < 2; tm++)
                        #pragma unroll
                        for (int tn = 0; tn < 4; tn++)
                            mma16816(acc2[tm][tn], af[tm], bf[tn]);
                }
                __syncthreads();
            }
        }
    }

    // ---- epilogue: /denom, +bo, store ----
    const int pb = wm * 32, ob = wn * 32;
    float2 bo2[4];
    #pragma unroll
    for (int tn = 0; tn < 4; tn++)
        bo2[tn] = *(const float2*)(bo + ob + tn * 8 + ncol);

    #pragma unroll
    for (int tm = 0; tm < 2; tm++) {
        #pragma unroll
        for (int h = 0; h < 2; h++) {
            int pair = pb + tm * 16 + mrow + h * 8;
            int i = pair >> 3, j = pair & 7;
            float invd = sInvd[pair];
            float* op = out + ((size_t)(i0 + i) * N_DIM + (j0 + j)) * C_OUT;
            #pragma unroll
            for (int tn = 0; tn < 4; tn++) {
                float2 v;
                v.x = acc2[tm][tn][h*2]   * invd + bo2[tn].x;
                v.y = acc2[tm][tn][h*2+1] * invd + bo2[tn].y;
                *(float2*)(op + ob + tn * 8 + ncol) = v;
            }
        }
    }
}

// ---------------------------------------------------------------------------
extern "C" void kernel_launch(void* const* d_in, const int* in_sizes, int n_in,
                              void* d_out, int out_size)
{
    const float* m     = (const float*)d_in[0];
    const int*   mask  = (const int*)  d_in[1];
    const float* gamma = (const float*)d_in[2];
    const float* beta  = (const float*)d_in[3];
    const float* Wa    = (const float*)d_in[4];
    const float* Wb    = (const float*)d_in[5];
    const float* Wo    = (const float*)d_in[6];
    const float* bo    = (const float*)d_in[7];
    float* out = (float*)d_out;

    cudaFuncSetAttribute(main_kernel, cudaFuncAttributeMaxDynamicSharedMemorySize, SMEM_BYTES);

    prep_kernel<<<N_DIM, 512>>>(m, mask, gamma, beta, Wa, Wb);
    wo_kernel<<<C_OUT, 256>>>(Wo);

    dim3 grid(N_DIM / 8, N_DIM / 8);
    main_kernel<<<grid, 256, SMEM_BYTES>>>(bo, out);
}

// round 7
// speedup vs baseline: 1.2668x; 1.2668x over previous
#include <cuda_runtime.h>
#include <cuda_fp16.h>
#include <cstdint>

#define N_DIM 384
#define S_DIM 64
#define C_IN  64
#define C_H   32
#define C_OUT 128
#define LN_EPS 1e-5f

// ---------------- device scratch ----------------
__device__ __half g_A[N_DIM * C_H * S_DIM];      // [n][c][s] fp16
__device__ __half g_B[N_DIM * C_H * S_DIM];      // [n][d][s] fp16
__device__ __half g_W[16 * C_OUT * 64];          // [cidx][o][kk] fp16
__device__ unsigned long long g_mbits[N_DIM];

#define SWZ(b) ((b) ^ (((b) >> 3) & 0x70))

__device__ __forceinline__ uint32_t smem_u32(const void* p) {
    uint32_t a;
    asm("{ .reg .u64 t; cvta.to.shared.u64 t, %1; cvt.u32.u64 %0, t; }" : "=r"(a) : "l"(p));
    return a;
}
__device__ __forceinline__ void ldsm4(uint32_t r[4], uint32_t a) {
    asm volatile("ldmatrix.sync.aligned.m8n8.x4.shared.b16 {%0,%1,%2,%3}, [%4];"
                 : "=r"(r[0]), "=r"(r[1]), "=r"(r[2]), "=r"(r[3]) : "r"(a));
}
__device__ __forceinline__ void mma16816(float c[4], const uint32_t a[4], const uint32_t b[2]) {
    asm volatile("mma.sync.aligned.m16n8k16.row.col.f32.f16.f16.f32 "
                 "{%0,%1,%2,%3}, {%4,%5,%6,%7}, {%8,%9}, {%0,%1,%2,%3};"
                 : "+f"(c[0]), "+f"(c[1]), "+f"(c[2]), "+f"(c[3])
                 : "r"(a[0]), "r"(a[1]), "r"(a[2]), "r"(a[3]), "r"(b[0]), "r"(b[1]));
}
// fp16-accumulator variant: D,C are 2 packed b32 regs
__device__ __forceinline__ void mma16816h(uint32_t c[2], const uint32_t a[4], const uint32_t b[2]) {
    asm volatile("mma.sync.aligned.m16n8k16.row.col.f16.f16.f16.f16 "
                 "{%0,%1}, {%2,%3,%4,%5}, {%6,%7}, {%0,%1};"
                 : "+r"(c[0]), "+r"(c[1])
                 : "r"(a[0]), "r"(a[1]), "r"(a[2]), "r"(a[3]), "r"(b[0]), "r"(b[1]));
}
#define CP16(dst, src) asm volatile("cp.async.cg.shared.global [%0], [%1], 16;" :: "r"(dst), "l"(src))
#define CP_COMMIT()    asm volatile("cp.async.commit_group;" ::: "memory")
#define CP_WAIT(n)     asm volatile("cp.async.wait_group %0;" :: "n"(n) : "memory")

// ---------------------------------------------------------------------------
// prep: LN + dual projection + mask -> fp16 [n][ch][s]; mask bitmasks
// one block per n, 512 threads
// ---------------------------------------------------------------------------
__global__ __launch_bounds__(512) void prep_kernel(
    const float* __restrict__ m, const int* __restrict__ mask,
    const float* __restrict__ gamma, const float* __restrict__ beta,
    const float* __restrict__ Wa, const float* __restrict__ Wb)
{
    __shared__ float sWaT[C_IN * C_H];
    __shared__ float sWbT[C_IN * C_H];
    __shared__ float sMn[16][C_IN];
    __shared__ float sa[C_H * 65];
    __shared__ float sb[C_H * 65];

    int tid = threadIdx.x, w = tid >> 5, l = tid & 31;
    int n = blockIdx.x;

    for (int i = tid; i < C_H * C_IN; i += 512) {
        int c = i >> 6, k = i & 63;
        sWaT[k * C_H + c] = Wa[i];
        sWbT[k * C_H + c] = Wb[i];
    }
    __syncthreads();

    float gam0 = gamma[l], gam1 = gamma[l + 32];
    float bet0 = beta[l],  bet1 = beta[l + 32];

    for (int it = 0; it < 4; it++) {
        int s = it * 16 + w;
        int row = s * N_DIM + n;
        const float* mp = m + (size_t)row * C_IN;
        float v0 = mp[l], v1 = mp[l + 32];
        float sum = v0 + v1;
        #pragma unroll
        for (int o = 16; o; o >>= 1) sum += __shfl_xor_sync(0xffffffffu, sum, o);
        float mu = sum * (1.f / 64.f);
        float d0 = v0 - mu, d1 = v1 - mu;
        float sq = d0 * d0 + d1 * d1;
        #pragma unroll
        for (int o = 16; o; o >>= 1) sq += __shfl_xor_sync(0xffffffffu, sq, o);
        float inv = rsqrtf(sq * (1.f / 64.f) + LN_EPS);
        sMn[w][l]      = d0 * inv * gam0 + bet0;
        sMn[w][l + 32] = d1 * inv * gam1 + bet1;
        __syncwarp();
        float mf = (float)mask[row];
        float aa = 0.f, bb = 0.f;
        #pragma unroll
        for (int k = 0; k < C_IN; k++) {
            float x = sMn[w][k];
            aa += x * sWaT[k * C_H + l];
            bb += x * sWbT[k * C_H + l];
        }
        sa[l * 65 + s] = aa * mf;
        sb[l * 65 + s] = bb * mf;
        __syncwarp();
    }
    __syncthreads();

    for (int e = tid; e < C_H * S_DIM; e += 512) {
        int c = e >> 6, s = e & 63;
        g_A[n * 2048 + e] = __float2half(sa[c * 65 + s]);
        g_B[n * 2048 + e] = __float2half(sb[c * 65 + s]);
    }

    if (w == 0) {
        unsigned b0 = __ballot_sync(0xffffffffu, mask[l * N_DIM + n] != 0);
        unsigned b1 = __ballot_sync(0xffffffffu, mask[(l + 32) * N_DIM + n] != 0);
        if (l == 0) g_mbits[n] = (unsigned long long)b0 | ((unsigned long long)b1 << 32);
    }
}

// ---------------------------------------------------------------------------
// Wo gather: g_W[cidx=sl*4+ksub][o][kk] = fp16(Wo[o][c*32+d])
//   c = sl*8 + ksub*2 + (kk>>5),  d = kk&31
// ---------------------------------------------------------------------------
__global__ __launch_bounds__(256) void wo_kernel(const float* __restrict__ Wo)
{
    __shared__ float rowv[1024];
    int o = blockIdx.x, tid = threadIdx.x;
    for (int i = tid; i < 1024; i += 256) rowv[i] = Wo[o * 1024 + i];
    __syncthreads();
    for (int r = tid; r < 1024; r += 256) {
        int cidx = r >> 6, kk = r & 63;
        int sl = cidx >> 2, ksub = cidx & 3;
        int c = sl * 8 + ksub * 2 + (kk >> 5), d = kk & 31;
        g_W[cidx * 8192 + o * 64 + kk] = __float2half(rowv[c * 32 + d]);
    }
}

// ---------------------------------------------------------------------------
// main: CTA = 8i x 8j = 64 pairs (R4 structure).
// GEMM1 (4 c-slices, fp32 acc) -> remap -> GEMM2 (16 chunks, fp16 acc in-chunk,
// fp32 cross-chunk).  smem: As 32K | Bs 32K | Zs 32K | Wo 2x16K | invd
// ---------------------------------------------------------------------------
#define OFF_AS 0u
#define OFF_BS 32768u
#define OFF_ZS 65536u
#define OFF_WO 98304u
#define OFF_IV 131072u
#define SMEM_BYTES (131072 + 256)

__global__ void __launch_bounds__(256, 1) main_kernel(
    const float* __restrict__ bo, float* __restrict__ out)
{
    extern __shared__ char sm[];
    const uint32_t smb = smem_u32(sm);
    const int tid = threadIdx.x, wid = tid >> 5, lane = tid & 31;
    const int i0 = blockIdx.y * 8, j0 = blockIdx.x * 8;
    float* sInvd = (float*)(sm + OFF_IV);

    if (tid < 64) {
        unsigned long long wv = g_mbits[i0 + (tid >> 3)] & g_mbits[j0 + (tid & 7)];
        sInvd[tid] = 1.f / fmaxf((float)__popcll(wv), 1.f);
    }

    // load A/B tiles (256 rows x 128B each, contiguous), swizzled
    {
        const char* srcA = (const char*)g_A + (size_t)i0 * 4096;
        const char* srcB = (const char*)g_B + (size_t)j0 * 4096;
        #pragma unroll
        for (int q = 0; q < 8; q++) {
            uint32_t rel = (uint32_t)(tid + q * 256) * 16u;
            uint32_t sw = SWZ(rel);
            *(uint4*)(sm + OFF_AS + sw) = *(const uint4*)(srcA + rel);
            *(uint4*)(sm + OFF_BS + sw) = *(const uint4*)(srcB + rel);
        }
    }

    // prefetch Wo chunk 0
    {
        const char* src = (const char*)g_W;
        #pragma unroll
        for (int q = 0; q < 4; q++) {
            uint32_t rel = (uint32_t)(tid + q * 256) * 16u;
            CP16(smb + OFF_WO + SWZ(rel), src + rel);
        }
        CP_COMMIT();
    }
    __syncthreads();

    const int wm = wid >> 2, wn = wid & 3;
    const int lr = lane & 15;
    const int lc = (lane >> 4) << 4;
    const int mrow = lane >> 2;
    const int ncol = (lane & 3) * 2;

    float acc2[2][4][4];
    #pragma unroll
    for (int a = 0; a < 2; a++)
        #pragma unroll
        for (int b = 0; b < 4; b++)
            #pragma unroll
            for (int c = 0; c < 4; c++) acc2[a][b][c] = 0.f;

    int cidx = 0;
    for (int sl = 0; sl < 4; sl++) {
        // ---- GEMM1 slice: M=64 ((i,c_l)), N=256 ((j,d)), K=64 (s), fp32 acc ----
        const int mb = wm * 32, nb = wn * 64;
        float acc1[2][8][4];
        #pragma unroll
        for (int a = 0; a < 2; a++)
            #pragma unroll
            for (int b = 0; b < 8; b++)
                #pragma unroll
                for (int c = 0; c < 4; c++) acc1[a][b][c] = 0.f;

        #pragma unroll
        for (int k = 0; k < 4; k++) {
            uint32_t af[2][4];
            #pragma unroll
            for (int tm = 0; tm < 2; tm++) {
                int mm = mb + tm * 16 + lr;
                int r = ((mm >> 3) << 5) + sl * 8 + (mm & 7);
                ldsm4(af[tm], smb + OFF_AS + SWZ((uint32_t)(r * 128 + k * 32 + lc)));
            }
            uint32_t bf[8][2];
            #pragma unroll
            for (int tp = 0; tp < 4; tp++) {
                uint32_t q[4];
                int nn = nb + tp * 16 + lr;
                ldsm4(q, smb + OFF_BS + SWZ((uint32_t)(nn * 128 + k * 32 + lc)));
                bf[2*tp][0] = q[0]; bf[2*tp+1][0] = q[1];
                bf[2*tp][1] = q[2]; bf[2*tp+1][1] = q[3];
            }
            #pragma unroll
            for (int tm = 0; tm < 2; tm++)
                #pragma unroll
                for (int tn = 0; tn < 8; tn++)
                    mma16816(acc1[tm][tn], af[tm], bf[tn]);
        }
        __syncthreads();   // previous GEMM2 chunk finished reading Zs

        // ---- remap Z -> Zs[ksub][pair][kk] fp16 ----
        #pragma unroll
        for (int tm = 0; tm < 2; tm++) {
            #pragma unroll
            for (int tn = 0; tn < 8; tn++) {
                int nn = nb + tn * 8 + ncol;
                int j = nn >> 5, d = nn & 31;
                #pragma unroll
                for (int h = 0; h < 2; h++) {
                    int mm = mb + tm * 16 + mrow + h * 8;
                    int i = mm >> 3, cl = mm & 7;
                    uint32_t rel = (uint32_t)((i * 8 + j) * 128 + ((cl & 1) * 32 + d) * 2);
                    __half2 hv = __floats2half2_rn(acc1[tm][tn][h*2], acc1[tm][tn][h*2+1]);
                    *(__half2*)(sm + OFF_ZS + (uint32_t)(cl >> 1) * 8192u + SWZ(rel)) = hv;
                }
            }
        }
        __syncthreads();

        // ---- GEMM2 chunks: M=64 pairs, N=128 o, K=64/chunk, f16 acc in-chunk ----
        const int pb = wm * 32, ob = wn * 32;
        for (int ksub = 0; ksub < 4; ksub++, cidx++) {
            if (cidx + 1 < 16) {
                const char* src = (const char*)g_W + (size_t)(cidx + 1) * 16384;
                uint32_t dst = smb + OFF_WO + (uint32_t)((cidx + 1) & 1) * 16384u;
                #pragma unroll
                for (int q = 0; q < 4; q++) {
                    uint32_t rel = (uint32_t)(tid + q * 256) * 16u;
                    CP16(dst + SWZ(rel), src + rel);
                }
                CP_COMMIT();
                CP_WAIT(1);
            } else {
                CP_WAIT(0);
            }
            __syncthreads();

            uint32_t zbase = smb + OFF_ZS + (uint32_t)ksub * 8192u;
            uint32_t wbase = smb + OFF_WO + (uint32_t)(cidx & 1) * 16384u;

            uint32_t cf[2][4][2];      // f16 chunk accumulators
            #pragma unroll
            for (int tm = 0; tm < 2; tm++)
                #pragma unroll
                for (int tn = 0; tn < 4; tn++) { cf[tm][tn][0] = 0u; cf[tm][tn][1] = 0u; }

            #pragma unroll
            for (int k = 0; k < 4; k++) {
                uint32_t af[2][4];
                #pragma unroll
                for (int tm = 0; tm < 2; tm++) {
                    int p = pb + tm * 16 + lr;
                    ldsm4(af[tm], zbase + SWZ((uint32_t)(p * 128 + k * 32 + lc)));
                }
                uint32_t bf[4][2];
                #pragma unroll
                for (int tp = 0; tp < 2; tp++) {
                    uint32_t q[4];
                    int o = ob + tp * 16 + lr;
                    ldsm4(q, wbase + SWZ((uint32_t)(o * 128 + k * 32 + lc)));
                    bf[2*tp][0] = q[0]; bf[2*tp+1][0] = q[1];
                    bf[2*tp][1] = q[2]; bf[2*tp+1][1] = q[3];
                }
                #pragma unroll
                for (int tm = 0; tm < 2; tm++)
                    #pragma unroll
                    for (int tn = 0; tn < 4; tn++)
                        mma16816h(cf[tm][tn], af[tm], bf[tn]);
            }

            // drain f16 chunk accumulators into fp32
            #pragma unroll
            for (int tm = 0; tm < 2; tm++)
                #pragma unroll
                for (int tn = 0; tn < 4; tn++) {
                    float2 f0 = __half22float2(*(__half2*)&cf[tm][tn][0]);
                    float2 f1 = __half22float2(*(__half2*)&cf[tm][tn][1]);
                    acc2[tm][tn][0] += f0.x;
                    acc2[tm][tn][1] += f0.y;
                    acc2[tm][tn][2] += f1.x;
                    acc2[tm][tn][3] += f1.y;
                }
            __syncthreads();
        }
    }

    // ---- epilogue: /denom, +bo, store ----
    const int pb = wm * 32, ob = wn * 32;
    float2 bo2[4];
    #pragma unroll
    for (int tn = 0; tn < 4; tn++)
        bo2[tn] = *(const float2*)(bo + ob + tn * 8 + ncol);

    #pragma unroll
    for (int tm = 0; tm < 2; tm++) {
        #pragma unroll
        for (int h = 0; h < 2; h++) {
            int pair = pb + tm * 16 + mrow + h * 8;
            int i = pair >> 3, j = pair & 7;
            float invd = sInvd[pair];
            float* op = out + ((size_t)(i0 + i) * N_DIM + (j0 + j)) * C_OUT;
            #pragma unroll
            for (int tn = 0; tn < 4; tn++) {
                float2 v;
                v.x = acc2[tm][tn][h*2]   * invd + bo2[tn].x;
                v.y = acc2[tm][tn][h*2+1] * invd + bo2[tn].y;
                *(float2*)(op + ob + tn * 8 + ncol) = v;
            }
        }
    }
}

// ---------------------------------------------------------------------------
extern "C" void kernel_launch(void* const* d_in, const int* in_sizes, int n_in,
                              void* d_out, int out_size)
{
    const float* m     = (const float*)d_in[0];
    const int*   mask  = (const int*)  d_in[1];
    const float* gamma = (const float*)d_in[2];
    const float* beta  = (const float*)d_in[3];
    const float* Wa    = (const float*)d_in[4];
    const float* Wb    = (const float*)d_in[5];
    const float* Wo    = (const float*)d_in[6];
    const float* bo    = (const float*)d_in[7];
    float* out = (float*)d_out;

    cudaFuncSetAttribute(main_kernel, cudaFuncAttributeMaxDynamicSharedMemorySize, SMEM_BYTES);

    prep_kernel<<<N_DIM, 512>>>(m, mask, gamma, beta, Wa, Wb);
    wo_kernel<<<C_OUT, 256>>>(Wo);

    dim3 grid(N_DIM / 8, N_DIM / 8);
    main_kernel<<<grid, 256, SMEM_BYTES>>>(bo, out);
}

// round 8
// speedup vs baseline: 1.2970x; 1.0238x over previous
#include <cuda_runtime.h>
#include <cuda_fp16.h>
#include <cstdint>

#define N_DIM 384
#define S_DIM 64
#define C_IN  64
#define C_H   32
#define C_OUT 128
#define LN_EPS 1e-5f

// ---------------- device scratch ----------------
__device__ __half g_A[N_DIM * C_H * S_DIM];      // [n][c][s] fp16
__device__ __half g_B[N_DIM * C_H * S_DIM];      // [n][d][s] fp16
__device__ __half g_W[16 * C_OUT * 64];          // [cidx][o][kk] fp16
__device__ unsigned long long g_mbits[N_DIM];

#define SWZ(b) ((b) ^ (((b) >> 3) & 0x70))

__device__ __forceinline__ uint32_t smem_u32(const void* p) {
    uint32_t a;
    asm("{ .reg .u64 t; cvta.to.shared.u64 t, %1; cvt.u32.u64 %0, t; }" : "=r"(a) : "l"(p));
    return a;
}
__device__ __forceinline__ void ldsm4(uint32_t r[4], uint32_t a) {
    asm volatile("ldmatrix.sync.aligned.m8n8.x4.shared.b16 {%0,%1,%2,%3}, [%4];"
                 : "=r"(r[0]), "=r"(r[1]), "=r"(r[2]), "=r"(r[3]) : "r"(a));
}
__device__ __forceinline__ void mma16816(float c[4], const uint32_t a[4], const uint32_t b[2]) {
    asm volatile("mma.sync.aligned.m16n8k16.row.col.f32.f16.f16.f32 "
                 "{%0,%1,%2,%3}, {%4,%5,%6,%7}, {%8,%9}, {%0,%1,%2,%3};"
                 : "+f"(c[0]), "+f"(c[1]), "+f"(c[2]), "+f"(c[3])
                 : "r"(a[0]), "r"(a[1]), "r"(a[2]), "r"(a[3]), "r"(b[0]), "r"(b[1]));
}
#define CP16(dst, src) asm volatile("cp.async.cg.shared.global [%0], [%1], 16;" :: "r"(dst), "l"(src))
#define CP_COMMIT()    asm volatile("cp.async.commit_group;" ::: "memory")
#define CP_WAIT(n)     asm volatile("cp.async.wait_group %0;" :: "n"(n) : "memory")

// ---------------------------------------------------------------------------
// prep: LN + dual projection + mask -> fp16 [n][ch][s]; mask bitmasks
// one block per n, 512 threads; weights transposed [c][k] with stride-68 pad
// ---------------------------------------------------------------------------
__global__ __launch_bounds__(512) void prep_kernel(
    const float* __restrict__ m, const int* __restrict__ mask,
    const float* __restrict__ gamma, const float* __restrict__ beta,
    const float* __restrict__ Wa, const float* __restrict__ Wb)
{
    __shared__ float sWa[C_H * 68];
    __shared__ float sWb[C_H * 68];
    __shared__ float sMn[16][C_IN];
    __shared__ float sa[C_H * 65];
    __shared__ float sb[C_H * 65];

    int tid = threadIdx.x, w = tid >> 5, l = tid & 31;
    int n = blockIdx.x;

    for (int i = tid; i < C_H * C_IN; i += 512) {
        int c = i >> 6, k = i & 63;
        sWa[c * 68 + k] = Wa[i];
        sWb[c * 68 + k] = Wb[i];
    }
    __syncthreads();

    float gam0 = gamma[l], gam1 = gamma[l + 32];
    float bet0 = beta[l],  bet1 = beta[l + 32];
    const float* wa = &sWa[l * 68];
    const float* wb = &sWb[l * 68];

    for (int it = 0; it < 4; it++) {
        int s = it * 16 + w;
        int row = s * N_DIM + n;
        const float* mp = m + (size_t)row * C_IN;
        float v0 = mp[l], v1 = mp[l + 32];
        float sum = v0 + v1;
        #pragma unroll
        for (int o = 16; o; o >>= 1) sum += __shfl_xor_sync(0xffffffffu, sum, o);
        float mu = sum * (1.f / 64.f);
        float d0 = v0 - mu, d1 = v1 - mu;
        float sq = d0 * d0 + d1 * d1;
        #pragma unroll
        for (int o = 16; o; o >>= 1) sq += __shfl_xor_sync(0xffffffffu, sq, o);
        float inv = rsqrtf(sq * (1.f / 64.f) + LN_EPS);
        sMn[w][l]      = d0 * inv * gam0 + bet0;
        sMn[w][l + 32] = d1 * inv * gam1 + bet1;
        __syncwarp();
        float mf = (float)mask[row];
        float aa = 0.f, bb = 0.f;
        #pragma unroll
        for (int k4 = 0; k4 < 16; k4++) {
            float4 x  = *(const float4*)&sMn[w][k4 * 4];
            float4 A4 = *(const float4*)&wa[k4 * 4];
            float4 B4 = *(const float4*)&wb[k4 * 4];
            aa += x.x * A4.x + x.y * A4.y + x.z * A4.z + x.w * A4.w;
            bb += x.x * B4.x + x.y * B4.y + x.z * B4.z + x.w * B4.w;
        }
        sa[l * 65 + s] = aa * mf;
        sb[l * 65 + s] = bb * mf;
        __syncwarp();
    }
    __syncthreads();

    for (int e = tid; e < C_H * S_DIM; e += 512) {
        int c = e >> 6, s = e & 63;
        g_A[n * 2048 + e] = __float2half(sa[c * 65 + s]);
        g_B[n * 2048 + e] = __float2half(sb[c * 65 + s]);
    }

    if (w == 0) {
        unsigned b0 = __ballot_sync(0xffffffffu, mask[l * N_DIM + n] != 0);
        unsigned b1 = __ballot_sync(0xffffffffu, mask[(l + 32) * N_DIM + n] != 0);
        if (l == 0) g_mbits[n] = (unsigned long long)b0 | ((unsigned long long)b1 << 32);
    }
}

// ---------------------------------------------------------------------------
// Wo gather
// ---------------------------------------------------------------------------
__global__ __launch_bounds__(256) void wo_kernel(const float* __restrict__ Wo)
{
    __shared__ float rowv[1024];
    int o = blockIdx.x, tid = threadIdx.x;
    for (int i = tid; i < 1024; i += 256) rowv[i] = Wo[o * 1024 + i];
    __syncthreads();
    for (int r = tid; r < 1024; r += 256) {
        int cidx = r >> 6, kk = r & 63;
        int sl = cidx >> 2, ksub = cidx & 3;
        int c = sl * 8 + ksub * 2 + (kk >> 5), d = kk & 31;
        g_W[cidx * 8192 + o * 64 + kk] = __float2half(rowv[c * 32 + d]);
    }
}

// ---------------------------------------------------------------------------
// main: CTA = 8i x 8j = 64 pairs, target 2 CTAs/SM.
// ---------------------------------------------------------------------------
#define OFF_AS 0u
#define OFF_BS 32768u
#define OFF_ZS 65536u
#define OFF_WO 98304u
#define OFF_IV 114688u
#define SMEM_BYTES (114688 + 256)

__global__ void __launch_bounds__(256, 2) main_kernel(
    const float* __restrict__ bo, float* __restrict__ out)
{
    extern __shared__ char sm[];
    const uint32_t smb = smem_u32(sm);
    const int tid = threadIdx.x, wid = tid >> 5, lane = tid & 31;
    const int i0 = blockIdx.y * 8, j0 = blockIdx.x * 8;
    float* sInvd = (float*)(sm + OFF_IV);

    if (tid < 64) {
        unsigned long long wv = g_mbits[i0 + (tid >> 3)] & g_mbits[j0 + (tid & 7)];
        sInvd[tid] = 1.f / fmaxf((float)__popcll(wv), 1.f);
    }

    // prefetch Wo chunk 0 (single buffer)
    {
        const char* src = (const char*)g_W;
        #pragma unroll
        for (int q = 0; q < 4; q++) {
            uint32_t rel = (uint32_t)(tid + q * 256) * 16u;
            CP16(smb + OFF_WO + SWZ(rel), src + rel);
        }
        CP_COMMIT();
    }

    // load A/B tiles
    {
        const char* srcA = (const char*)g_A + (size_t)i0 * 4096;
        const char* srcB = (const char*)g_B + (size_t)j0 * 4096;
        #pragma unroll
        for (int q = 0; q < 8; q++) {
            uint32_t rel = (uint32_t)(tid + q * 256) * 16u;
            uint32_t sw = SWZ(rel);
            *(uint4*)(sm + OFF_AS + sw) = *(const uint4*)(srcA + rel);
            *(uint4*)(sm + OFF_BS + sw) = *(const uint4*)(srcB + rel);
        }
    }
    __syncthreads();

    const int wm = wid >> 2, wn = wid & 3;
    const int lr = lane & 15;
    const int lc = (lane >> 4) << 4;
    const int mrow = lane >> 2;
    const int ncol = (lane & 3) * 2;

    float acc2[2][4][4];
    #pragma unroll
    for (int a = 0; a < 2; a++)
        #pragma unroll
        for (int b = 0; b < 4; b++)
            #pragma unroll
            for (int c = 0; c < 4; c++) acc2[a][b][c] = 0.f;

    int cidx = 0;
    for (int sl = 0; sl < 4; sl++) {
        const int mb = wm * 32, nb = wn * 64;

        // ---- GEMM1 slice in two N-halves (acc1 32 regs each) ----
        #pragma unroll
        for (int nh = 0; nh < 2; nh++) {
            float acc1[2][4][4];
            #pragma unroll
            for (int a = 0; a < 2; a++)
                #pragma unroll
                for (int b = 0; b < 4; b++)
                    #pragma unroll
                    for (int c = 0; c < 4; c++) acc1[a][b][c] = 0.f;

            #pragma unroll
            for (int k = 0; k < 4; k++) {
                uint32_t af[2][4];
                #pragma unroll
                for (int tm = 0; tm < 2; tm++) {
                    int mm = mb + tm * 16 + lr;
                    int r = ((mm >> 3) << 5) + sl * 8 + (mm & 7);
                    ldsm4(af[tm], smb + OFF_AS + SWZ((uint32_t)(r * 128 + k * 32 + lc)));
                }
                uint32_t bf[4][2];
                #pragma unroll
                for (int tp = 0; tp < 2; tp++) {
                    uint32_t q[4];
                    int nn = nb + nh * 32 + tp * 16 + lr;
                    ldsm4(q, smb + OFF_BS + SWZ((uint32_t)(nn * 128 + k * 32 + lc)));
                    bf[2*tp][0] = q[0]; bf[2*tp+1][0] = q[1];
                    bf[2*tp][1] = q[2]; bf[2*tp+1][1] = q[3];
                }
                #pragma unroll
                for (int tm = 0; tm < 2; tm++)
                    #pragma unroll
                    for (int tn = 0; tn < 4; tn++)
                        mma16816(acc1[tm][tn], af[tm], bf[tn]);
            }

            // remap this N-half -> Zs
            #pragma unroll
            for (int tm = 0; tm < 2; tm++) {
                #pragma unroll
                for (int tn = 0; tn < 4; tn++) {
                    int nn = nb + nh * 32 + tn * 8 + ncol;
                    int j = nn >> 5, d = nn & 31;
                    #pragma unroll
                    for (int h = 0; h < 2; h++) {
                        int mm = mb + tm * 16 + mrow + h * 8;
                        int i = mm >> 3, cl = mm & 7;
                        uint32_t rel = (uint32_t)((i * 8 + j) * 128 + ((cl & 1) * 32 + d) * 2);
                        __half2 hv = __floats2half2_rn(acc1[tm][tn][h*2], acc1[tm][tn][h*2+1]);
                        *(__half2*)(sm + OFF_ZS + (uint32_t)(cl >> 1) * 8192u + SWZ(rel)) = hv;
                    }
                }
            }
        }
        __syncthreads();   // remap visible; prev chunks already synced

        // ---- GEMM2: 4 chunks, single Wo buffer ----
        const int pb = wm * 32, ob = wn * 32;
        for (int ksub = 0; ksub < 4; ksub++, cidx++) {
            CP_WAIT(0);
            __syncthreads();

            uint32_t zbase = smb + OFF_ZS + (uint32_t)ksub * 8192u;
            uint32_t wbase = smb + OFF_WO;
            #pragma unroll
            for (int k = 0; k < 4; k++) {
                uint32_t af[2][4];
                #pragma unroll
                for (int tm = 0; tm < 2; tm++) {
                    int p = pb + tm * 16 + lr;
                    ldsm4(af[tm], zbase + SWZ((uint32_t)(p * 128 + k * 32 + lc)));
                }
                uint32_t bf[4][2];
                #pragma unroll
                for (int tp = 0; tp < 2; tp++) {
                    uint32_t q[4];
                    int o = ob + tp * 16 + lr;
                    ldsm4(q, wbase + SWZ((uint32_t)(o * 128 + k * 32 + lc)));
                    bf[2*tp][0] = q[0]; bf[2*tp+1][0] = q[1];
                    bf[2*tp][1] = q[2]; bf[2*tp+1][1] = q[3];
                }
                #pragma unroll
                for (int tm = 0; tm < 2; tm++)
                    #pragma unroll
                    for (int tn = 0; tn < 4; tn++)
                        mma16816(acc2[tm][tn], af[tm], bf[tn]);
            }
            __syncthreads();

            if (cidx + 1 < 16) {
                const char* src = (const char*)g_W + (size_t)(cidx + 1) * 16384;
                #pragma unroll
                for (int q = 0; q < 4; q++) {
                    uint32_t rel = (uint32_t)(tid + q * 256) * 16u;
                    CP16(smb + OFF_WO + SWZ(rel), src + rel);
                }
                CP_COMMIT();
            }
        }
    }

    // ---- epilogue ----
    const int pb = wm * 32, ob = wn * 32;
    float2 bo2[4];
    #pragma unroll
    for (int tn = 0; tn < 4; tn++)
        bo2[tn] = *(const float2*)(bo + ob + tn * 8 + ncol);

    #pragma unroll
    for (int tm = 0; tm < 2; tm++) {
        #pragma unroll
        for (int h = 0; h < 2; h++) {
            int pair = pb + tm * 16 + mrow + h * 8;
            int i = pair >> 3, j = pair & 7;
            float invd = sInvd[pair];
            float* op = out + ((size_t)(i0 + i) * N_DIM + (j0 + j)) * C_OUT;
            #pragma unroll
            for (int tn = 0; tn < 4; tn++) {
                float2 v;
                v.x = acc2[tm][tn][h*2]   * invd + bo2[tn].x;
                v.y = acc2[tm][tn][h*2+1] * invd + bo2[tn].y;
                *(float2*)(op + ob + tn * 8 + ncol) = v;
            }
        }
    }
}

// ---------------------------------------------------------------------------
extern "C" void kernel_launch(void* const* d_in, const int* in_sizes, int n_in,
                              void* d_out, int out_size)
{
    const float* m     = (const float*)d_in[0];
    const int*   mask  = (const int*)  d_in[1];
    const float* gamma = (const float*)d_in[2];
    const float* beta  = (const float*)d_in[3];
    const float* Wa    = (const float*)d_in[4];
    const float* Wb    = (const float*)d_in[5];
    const float* Wo    = (const float*)d_in[6];
    const float* bo    = (const float*)d_in[7];
    float* out = (float*)d_out;

    cudaFuncSetAttribute(main_kernel, cudaFuncAttributeMaxDynamicSharedMemorySize, SMEM_BYTES);

    prep_kernel<<<N_DIM, 512>>>(m, mask, gamma, beta, Wa, Wb);
    wo_kernel<<<C_OUT, 256>>>(Wo);

    dim3 grid(N_DIM / 8, N_DIM / 8);
    main_kernel<<<grid, 256, SMEM_BYTES>>>(bo, out);
}

// round 9
// speedup vs baseline: 1.3646x; 1.0521x over previous
#include <cuda_runtime.h>
#include <cuda_fp16.h>
#include <cstdint>

#define N_DIM 384
#define S_DIM 64
#define C_IN  64
#define C_H   32
#define C_OUT 128
#define LN_EPS 1e-5f

// ---------------- device scratch ----------------
__device__ __half g_A[N_DIM * C_H * S_DIM];      // [n][c][s] fp16
__device__ __half g_B[N_DIM * C_H * S_DIM];      // [n][d][s] fp16
__device__ __half g_W[16 * C_OUT * 64];          // [cidx][o][kk] fp16
__device__ unsigned long long g_mbits[N_DIM];

#define SWZ(b) ((b) ^ (((b) >> 3) & 0x70))

__device__ __forceinline__ uint32_t smem_u32(const void* p) {
    uint32_t a;
    asm("{ .reg .u64 t; cvta.to.shared.u64 t, %1; cvt.u32.u64 %0, t; }" : "=r"(a) : "l"(p));
    return a;
}
__device__ __forceinline__ void ldsm4(uint32_t r[4], uint32_t a) {
    asm volatile("ldmatrix.sync.aligned.m8n8.x4.shared.b16 {%0,%1,%2,%3}, [%4];"
                 : "=r"(r[0]), "=r"(r[1]), "=r"(r[2]), "=r"(r[3]) : "r"(a));
}
__device__ __forceinline__ void mma16816(float c[4], const uint32_t a[4], const uint32_t b[2]) {
    asm volatile("mma.sync.aligned.m16n8k16.row.col.f32.f16.f16.f32 "
                 "{%0,%1,%2,%3}, {%4,%5,%6,%7}, {%8,%9}, {%0,%1,%2,%3};"
                 : "+f"(c[0]), "+f"(c[1]), "+f"(c[2]), "+f"(c[3])
                 : "r"(a[0]), "r"(a[1]), "r"(a[2]), "r"(a[3]), "r"(b[0]), "r"(b[1]));
}
#define CP16(dst, src) asm volatile("cp.async.cg.shared.global [%0], [%1], 16;" :: "r"(dst), "l"(src))
#define CP_COMMIT()    asm volatile("cp.async.commit_group;" ::: "memory")
#define CP_WAIT(n)     asm volatile("cp.async.wait_group %0;" :: "n"(n) : "memory")

// ---------------------------------------------------------------------------
// prep: LN + dual projection + mask -> fp16 [n][ch][s]; mask bitmasks
// one block per n, 512 threads; reg-capped for 3 blocks/SM; fp16 staging
// ---------------------------------------------------------------------------
__global__ __launch_bounds__(512, 3) void prep_kernel(
    const float* __restrict__ m, const int* __restrict__ mask,
    const float* __restrict__ gamma, const float* __restrict__ beta,
    const float* __restrict__ Wa, const float* __restrict__ Wb)
{
    __shared__ float sWa[C_H * 68];     // [c][k], stride-68 pad (conflict-free float4)
    __shared__ float sWb[C_H * 68];
    __shared__ float sMn[16][C_IN];
    __shared__ __half sa[C_H * 66];     // [c][s], stride 66
    __shared__ __half sb[C_H * 66];

    int tid = threadIdx.x, w = tid >> 5, l = tid & 31;
    int n = blockIdx.x;

    for (int i = tid; i < C_H * C_IN; i += 512) {
        int c = i >> 6, k = i & 63;
        sWa[c * 68 + k] = Wa[i];
        sWb[c * 68 + k] = Wb[i];
    }
    __syncthreads();

    float gam0 = gamma[l], gam1 = gamma[l + 32];
    float bet0 = beta[l],  bet1 = beta[l + 32];
    const float* wa = &sWa[l * 68];
    const float* wb = &sWb[l * 68];

    for (int it = 0; it < 4; it++) {
        int s = it * 16 + w;
        int row = s * N_DIM + n;
        const float* mp = m + (size_t)row * C_IN;
        float v0 = mp[l], v1 = mp[l + 32];
        float sum = v0 + v1;
        #pragma unroll
        for (int o = 16; o; o >>= 1) sum += __shfl_xor_sync(0xffffffffu, sum, o);
        float mu = sum * (1.f / 64.f);
        float d0 = v0 - mu, d1 = v1 - mu;
        float sq = d0 * d0 + d1 * d1;
        #pragma unroll
        for (int o = 16; o; o >>= 1) sq += __shfl_xor_sync(0xffffffffu, sq, o);
        float inv = rsqrtf(sq * (1.f / 64.f) + LN_EPS);
        sMn[w][l]      = d0 * inv * gam0 + bet0;
        sMn[w][l + 32] = d1 * inv * gam1 + bet1;
        __syncwarp();
        float mf = (float)mask[row];
        float aa = 0.f, bb = 0.f;
        #pragma unroll
        for (int k4 = 0; k4 < 16; k4++) {
            float4 x  = *(const float4*)&sMn[w][k4 * 4];
            float4 A4 = *(const float4*)&wa[k4 * 4];
            float4 B4 = *(const float4*)&wb[k4 * 4];
            aa += x.x * A4.x + x.y * A4.y + x.z * A4.z + x.w * A4.w;
            bb += x.x * B4.x + x.y * B4.y + x.z * B4.z + x.w * B4.w;
        }
        sa[l * 66 + s] = __float2half(aa * mf);
        sb[l * 66 + s] = __float2half(bb * mf);
        __syncwarp();
    }
    __syncthreads();

    for (int e = tid; e < C_H * S_DIM; e += 512) {
        int c = e >> 6, s = e & 63;
        g_A[n * 2048 + e] = sa[c * 66 + s];
        g_B[n * 2048 + e] = sb[c * 66 + s];
    }

    if (w == 0) {
        unsigned b0 = __ballot_sync(0xffffffffu, mask[l * N_DIM + n] != 0);
        unsigned b1 = __ballot_sync(0xffffffffu, mask[(l + 32) * N_DIM + n] != 0);
        if (l == 0) g_mbits[n] = (unsigned long long)b0 | ((unsigned long long)b1 << 32);
    }
}

// ---------------------------------------------------------------------------
// Wo gather: g_W[cidx=sl*4+ksub][o][kk] = fp16(Wo[o][c*32+d])
//   c = sl*8 + ksub*2 + (kk>>5),  d = kk&31
// ---------------------------------------------------------------------------
__global__ __launch_bounds__(256) void wo_kernel(const float* __restrict__ Wo)
{
    __shared__ float rowv[1024];
    int o = blockIdx.x, tid = threadIdx.x;
    for (int i = tid; i < 1024; i += 256) rowv[i] = Wo[o * 1024 + i];
    __syncthreads();
    for (int r = tid; r < 1024; r += 256) {
        int cidx = r >> 6, kk = r & 63;
        int sl = cidx >> 2, ksub = cidx & 3;
        int c = sl * 8 + ksub * 2 + (kk >> 5), d = kk & 31;
        g_W[cidx * 8192 + o * 64 + kk] = __float2half(rowv[c * 32 + d]);
    }
}

// ---------------------------------------------------------------------------
// main: CTA = 8i x 8j = 64 pairs (R4 structure, single barrier per chunk).
// smem: As 32K | Bs 32K | Zs 32K | Wo 2x16K | invd
// ---------------------------------------------------------------------------
#define OFF_AS 0u
#define OFF_BS 32768u
#define OFF_ZS 65536u
#define OFF_WO 98304u
#define OFF_IV 131072u
#define SMEM_BYTES (131072 + 256)

__global__ void __launch_bounds__(256, 1) main_kernel(
    const float* __restrict__ bo, float* __restrict__ out)
{
    extern __shared__ char sm[];
    const uint32_t smb = smem_u32(sm);
    const int tid = threadIdx.x, wid = tid >> 5, lane = tid & 31;
    const int i0 = blockIdx.y * 8, j0 = blockIdx.x * 8;
    float* sInvd = (float*)(sm + OFF_IV);

    if (tid < 64) {
        unsigned long long wv = g_mbits[i0 + (tid >> 3)] & g_mbits[j0 + (tid & 7)];
        sInvd[tid] = 1.f / fmaxf((float)__popcll(wv), 1.f);
    }

    // prefetch Wo chunk 0 into buf0
    {
        const char* src = (const char*)g_W;
        #pragma unroll
        for (int q = 0; q < 4; q++) {
            uint32_t rel = (uint32_t)(tid + q * 256) * 16u;
            CP16(smb + OFF_WO + SWZ(rel), src + rel);
        }
        CP_COMMIT();
    }

    // load A/B tiles (256 rows x 128B each, contiguous), swizzled
    {
        const char* srcA = (const char*)g_A + (size_t)i0 * 4096;
        const char* srcB = (const char*)g_B + (size_t)j0 * 4096;
        #pragma unroll
        for (int q = 0; q < 8; q++) {
            uint32_t rel = (uint32_t)(tid + q * 256) * 16u;
            uint32_t sw = SWZ(rel);
            *(uint4*)(sm + OFF_AS + sw) = *(const uint4*)(srcA + rel);
            *(uint4*)(sm + OFF_BS + sw) = *(const uint4*)(srcB + rel);
        }
    }
    __syncthreads();

    const int wm = wid >> 2, wn = wid & 3;
    const int lr = lane & 15;
    const int lc = (lane >> 4) << 4;
    const int mrow = lane >> 2;
    const int ncol = (lane & 3) * 2;

    float acc2[2][4][4];
    #pragma unroll
    for (int a = 0; a < 2; a++)
        #pragma unroll
        for (int b = 0; b < 4; b++)
            #pragma unroll
            for (int c = 0; c < 4; c++) acc2[a][b][c] = 0.f;

    int cidx = 0;
    for (int sl = 0; sl < 4; sl++) {
        // ---- GEMM1 slice: M=64 ((i,c_l)), N=256 ((j,d)), K=64 (s), fp32 acc ----
        const int mb = wm * 32, nb = wn * 64;
        float acc1[2][8][4];
        #pragma unroll
        for (int a = 0; a < 2; a++)
            #pragma unroll
            for (int b = 0; b < 8; b++)
                #pragma unroll
                for (int c = 0; c < 4; c++) acc1[a][b][c] = 0.f;

        #pragma unroll
        for (int k = 0; k < 4; k++) {
            uint32_t af[2][4];
            #pragma unroll
            for (int tm = 0; tm < 2; tm++) {
                int mm = mb + tm * 16 + lr;
                int r = ((mm >> 3) << 5) + sl * 8 + (mm & 7);
                ldsm4(af[tm], smb + OFF_AS + SWZ((uint32_t)(r * 128 + k * 32 + lc)));
            }
            uint32_t bf[8][2];
            #pragma unroll
            for (int tp = 0; tp < 4; tp++) {
                uint32_t q[4];
                int nn = nb + tp * 16 + lr;
                ldsm4(q, smb + OFF_BS + SWZ((uint32_t)(nn * 128 + k * 32 + lc)));
                bf[2*tp][0] = q[0]; bf[2*tp+1][0] = q[1];
                bf[2*tp][1] = q[2]; bf[2*tp+1][1] = q[3];
            }
            #pragma unroll
            for (int tm = 0; tm < 2; tm++)
                #pragma unroll
                for (int tn = 0; tn < 8; tn++)
                    mma16816(acc1[tm][tn], af[tm], bf[tn]);
        }
        __syncthreads();   // S1: all warps done reading Zs (prev sl chunk 3)

        // ---- remap Z -> Zs[ksub][pair][kk] fp16 ----
        #pragma unroll
        for (int tm = 0; tm < 2; tm++) {
            #pragma unroll
            for (int tn = 0; tn < 8; tn++) {
                int nn = nb + tn * 8 + ncol;
                int j = nn >> 5, d = nn & 31;
                #pragma unroll
                for (int h = 0; h < 2; h++) {
                    int mm = mb + tm * 16 + mrow + h * 8;
                    int i = mm >> 3, cl = mm & 7;
                    uint32_t rel = (uint32_t)((i * 8 + j) * 128 + ((cl & 1) * 32 + d) * 2);
                    __half2 hv = __floats2half2_rn(acc1[tm][tn][h*2], acc1[tm][tn][h*2+1]);
                    *(__half2*)(sm + OFF_ZS + (uint32_t)(cl >> 1) * 8192u + SWZ(rel)) = hv;
                }
            }
        }
        __syncthreads();   // S2: remap visible

        // ---- GEMM2: 4 chunks, one barrier per chunk ----
        const int pb = wm * 32, ob = wn * 32;
        for (int ksub = 0; ksub < 4; ksub++, cidx++) {
            CP_WAIT(0);        // W[cidx] landed (only outstanding group)
            __syncthreads();   // S3: visibility + all warps done with buf[(cidx-1)&1]

            // prefetch W[cidx+1] into the OTHER buffer (nobody reads it this chunk)
            if (cidx + 1 < 16) {
                const char* src = (const char*)g_W + (size_t)(cidx + 1) * 16384;
                uint32_t dst = smb + OFF_WO + (uint32_t)((cidx + 1) & 1) * 16384u;
                #pragma unroll
                for (int q = 0; q < 4; q++) {
                    uint32_t rel = (uint32_t)(tid + q * 256) * 16u;
                    CP16(dst + SWZ(rel), src + rel);
                }
                CP_COMMIT();
            }

            uint32_t zbase = smb + OFF_ZS + (uint32_t)ksub * 8192u;
            uint32_t wbase = smb + OFF_WO + (uint32_t)(cidx & 1) * 16384u;
            #pragma unroll
            for (int k = 0; k < 4; k++) {
                uint32_t af[2][4];
                #pragma unroll
                for (int tm = 0; tm < 2; tm++) {
                    int p = pb + tm * 16 + lr;
                    ldsm4(af[tm], zbase + SWZ((uint32_t)(p * 128 + k * 32 + lc)));
                }
                uint32_t bf[4][2];
                #pragma unroll
                for (int tp = 0; tp < 2; tp++) {
                    uint32_t q[4];
                    int o = ob + tp * 16 + lr;
                    ldsm4(q, wbase + SWZ((uint32_t)(o * 128 + k * 32 + lc)));
                    bf[2*tp][0] = q[0]; bf[2*tp+1][0] = q[1];
                    bf[2*tp][1] = q[2]; bf[2*tp+1][1] = q[3];
                }
                #pragma unroll
                for (int tm = 0; tm < 2; tm++)
                    #pragma unroll
                    for (int tn = 0; tn < 4; tn++)
                        mma16816(acc2[tm][tn], af[tm], bf[tn]);
            }
            // no trailing barrier: next chunk's S3 orders buffer reuse
        }
    }

    // ---- epilogue: /denom, +bo, store ----
    const int pb = wm * 32, ob = wn * 32;
    float2 bo2[4];
    #pragma unroll
    for (int tn = 0; tn < 4; tn++)
        bo2[tn] = *(const float2*)(bo + ob + tn * 8 + ncol);

    #pragma unroll
    for (int tm = 0; tm < 2; tm++) {
        #pragma unroll
        for (int h = 0; h < 2; h++) {
            int pair = pb + tm * 16 + mrow + h * 8;
            int i = pair >> 3, j = pair & 7;
            float invd = sInvd[pair];
            float* op = out + ((size_t)(i0 + i) * N_DIM + (j0 + j)) * C_OUT;
            #pragma unroll
            for (int tn = 0; tn < 4; tn++) {
                float2 v;
                v.x = acc2[tm][tn][h*2]   * invd + bo2[tn].x;
                v.y = acc2[tm][tn][h*2+1] * invd + bo2[tn].y;
                *(float2*)(op + ob + tn * 8 + ncol) = v;
            }
        }
    }
}

// ---------------------------------------------------------------------------
extern "C" void kernel_launch(void* const* d_in, const int* in_sizes, int n_in,
                              void* d_out, int out_size)
{
    const float* m     = (const float*)d_in[0];
    const int*   mask  = (const int*)  d_in[1];
    const float* gamma = (const float*)d_in[2];
    const float* beta  = (const float*)d_in[3];
    const float* Wa    = (const float*)d_in[4];
    const float* Wb    = (const float*)d_in[5];
    const float* Wo    = (const float*)d_in[6];
    const float* bo    = (const float*)d_in[7];
    float* out = (float*)d_out;

    cudaFuncSetAttribute(main_kernel, cudaFuncAttributeMaxDynamicSharedMemorySize, SMEM_BYTES);

    prep_kernel<<<N_DIM, 512>>>(m, mask, gamma, beta, Wa, Wb);
    wo_kernel<<<C_OUT, 256>>>(Wo);

    dim3 grid(N_DIM / 8, N_DIM / 8);
    main_kernel<<<grid, 256, SMEM_BYTES>>>(bo, out);
}

// round 10
// speedup vs baseline: 1.3807x; 1.0118x over previous
#include <cuda_runtime.h>
#include <cuda_fp16.h>
#include <cstdint>

#define N_DIM 384
#define S_DIM 64
#define C_IN  64
#define C_H   32
#define C_OUT 128
#define LN_EPS 1e-5f

// ---------------- device scratch ----------------
__device__ __half g_A[N_DIM * C_H * S_DIM];      // [n][c][s] fp16
__device__ __half g_B[N_DIM * C_H * S_DIM];      // [n][d][s] fp16
__device__ __half g_W[16 * C_OUT * 64];          // [cidx][o][kk] fp16
__device__ unsigned long long g_mbits[N_DIM];

#define SWZ(b) ((b) ^ (((b) >> 3) & 0x70))

__device__ __forceinline__ uint32_t smem_u32(const void* p) {
    uint32_t a;
    asm("{ .reg .u64 t; cvta.to.shared.u64 t, %1; cvt.u32.u64 %0, t; }" : "=r"(a) : "l"(p));
    return a;
}
__device__ __forceinline__ void ldsm4(uint32_t r[4], uint32_t a) {
    asm volatile("ldmatrix.sync.aligned.m8n8.x4.shared.b16 {%0,%1,%2,%3}, [%4];"
                 : "=r"(r[0]), "=r"(r[1]), "=r"(r[2]), "=r"(r[3]) : "r"(a));
}
__device__ __forceinline__ void mma16816(float c[4], const uint32_t a[4], const uint32_t b[2]) {
    asm volatile("mma.sync.aligned.m16n8k16.row.col.f32.f16.f16.f32 "
                 "{%0,%1,%2,%3}, {%4,%5,%6,%7}, {%8,%9}, {%0,%1,%2,%3};"
                 : "+f"(c[0]), "+f"(c[1]), "+f"(c[2]), "+f"(c[3])
                 : "r"(a[0]), "r"(a[1]), "r"(a[2]), "r"(a[3]), "r"(b[0]), "r"(b[1]));
}
#define CP16(dst, src) asm volatile("cp.async.cg.shared.global [%0], [%1], 16;" :: "r"(dst), "l"(src))
#define CP_COMMIT()    asm volatile("cp.async.commit_group;" ::: "memory")
#define CP_WAIT(n)     asm volatile("cp.async.wait_group %0;" :: "n"(n) : "memory")

// ---------------------------------------------------------------------------
// fused prep + wo kernel.
//   blocks [0, 768):  prep for n = b>>1, s-half = b&1 (32 s values)
//   blocks [768, 896): wo gather for o = b - 768
// ---------------------------------------------------------------------------
__global__ __launch_bounds__(512, 3) void prep_kernel(
    const float* __restrict__ m, const int* __restrict__ mask,
    const float* __restrict__ gamma, const float* __restrict__ beta,
    const float* __restrict__ Wa, const float* __restrict__ Wb,
    const float* __restrict__ Wo)
{
    __shared__ float sWa[C_H * 68];     // [c][k], stride-68 pad
    __shared__ float sWb[C_H * 68];
    __shared__ float sMn[16][C_IN];
    __shared__ __half sa[C_H * 34];     // [c][sloc], stride 34
    __shared__ __half sb[C_H * 34];

    int tid = threadIdx.x, w = tid >> 5, l = tid & 31;
    int b = blockIdx.x;

    if (b >= 2 * N_DIM) {
        // ---- Wo gather: g_W[cidx][o][kk] = fp16(Wo[o][c*32+d]) ----
        __shared__ float rowv[1024];
        int o = b - 2 * N_DIM;
        for (int i = tid; i < 1024; i += 512) rowv[i] = Wo[o * 1024 + i];
        __syncthreads();
        for (int r = tid; r < 1024; r += 512) {
            int cidx = r >> 6, kk = r & 63;
            int sl = cidx >> 2, ksub = cidx & 3;
            int c = sl * 8 + ksub * 2 + (kk >> 5), d = kk & 31;
            g_W[cidx * 8192 + o * 64 + kk] = __float2half(rowv[c * 32 + d]);
        }
        return;
    }

    int n = b >> 1, sh = b & 1;

    for (int i = tid; i < C_H * C_IN; i += 512) {
        int c = i >> 6, k = i & 63;
        sWa[c * 68 + k] = Wa[i];
        sWb[c * 68 + k] = Wb[i];
    }
    __syncthreads();

    float gam0 = gamma[l], gam1 = gamma[l + 32];
    float bet0 = beta[l],  bet1 = beta[l + 32];
    const float* wa = &sWa[l * 68];
    const float* wb = &sWb[l * 68];

    #pragma unroll
    for (int it = 0; it < 2; it++) {
        int sloc = it * 16 + w;
        int s = sh * 32 + sloc;
        int row = s * N_DIM + n;
        const float* mp = m + (size_t)row * C_IN;
        float v0 = mp[l], v1 = mp[l + 32];
        float sum = v0 + v1;
        #pragma unroll
        for (int o = 16; o; o >>= 1) sum += __shfl_xor_sync(0xffffffffu, sum, o);
        float mu = sum * (1.f / 64.f);
        float d0 = v0 - mu, d1 = v1 - mu;
        float sq = d0 * d0 + d1 * d1;
        #pragma unroll
        for (int o = 16; o; o >>= 1) sq += __shfl_xor_sync(0xffffffffu, sq, o);
        float inv = rsqrtf(sq * (1.f / 64.f) + LN_EPS);
        sMn[w][l]      = d0 * inv * gam0 + bet0;
        sMn[w][l + 32] = d1 * inv * gam1 + bet1;
        __syncwarp();
        float mf = (float)mask[row];
        float aa = 0.f, bb = 0.f;
        #pragma unroll
        for (int k4 = 0; k4 < 16; k4++) {
            float4 x  = *(const float4*)&sMn[w][k4 * 4];
            float4 A4 = *(const float4*)&wa[k4 * 4];
            float4 B4 = *(const float4*)&wb[k4 * 4];
            aa += x.x * A4.x + x.y * A4.y + x.z * A4.z + x.w * A4.w;
            bb += x.x * B4.x + x.y * B4.y + x.z * B4.z + x.w * B4.w;
        }
        sa[l * 34 + sloc] = __float2half(aa * mf);
        sb[l * 34 + sloc] = __float2half(bb * mf);
        __syncwarp();
    }
    __syncthreads();

    // write out: g_A[n][c][sh*32 + sloc], 1024 halfs each
    for (int e = tid; e < C_H * 32; e += 512) {
        int c = e >> 5, sloc = e & 31;
        size_t go = (size_t)n * 2048 + (size_t)c * 64 + sh * 32 + sloc;
        g_A[go] = sa[c * 34 + sloc];
        g_B[go] = sb[c * 34 + sloc];
    }

    // mask bitmask (once per n, from the sh==0 block)
    if (sh == 0 && w == 0) {
        unsigned b0 = __ballot_sync(0xffffffffu, mask[l * N_DIM + n] != 0);
        unsigned b1 = __ballot_sync(0xffffffffu, mask[(l + 32) * N_DIM + n] != 0);
        if (l == 0) g_mbits[n] = (unsigned long long)b0 | ((unsigned long long)b1 << 32);
    }
}

// ---------------------------------------------------------------------------
// main: CTA = 8i x 8j = 64 pairs (at legacy-HMMA issue floor).
// smem: As 32K | Bs 32K | Zs 32K | Wo 2x16K | invd
// ---------------------------------------------------------------------------
#define OFF_AS 0u
#define OFF_BS 32768u
#define OFF_ZS 65536u
#define OFF_WO 98304u
#define OFF_IV 131072u
#define SMEM_BYTES (131072 + 256)

__global__ void __launch_bounds__(256, 1) main_kernel(
    const float* __restrict__ bo, float* __restrict__ out)
{
    extern __shared__ char sm[];
    const uint32_t smb = smem_u32(sm);
    const int tid = threadIdx.x, wid = tid >> 5, lane = tid & 31;
    const int i0 = blockIdx.y * 8, j0 = blockIdx.x * 8;
    float* sInvd = (float*)(sm + OFF_IV);

    if (tid < 64) {
        unsigned long long wv = g_mbits[i0 + (tid >> 3)] & g_mbits[j0 + (tid & 7)];
        sInvd[tid] = 1.f / fmaxf((float)__popcll(wv), 1.f);
    }

    // prefetch Wo chunk 0 into buf0
    {
        const char* src = (const char*)g_W;
        #pragma unroll
        for (int q = 0; q < 4; q++) {
            uint32_t rel = (uint32_t)(tid + q * 256) * 16u;
            CP16(smb + OFF_WO + SWZ(rel), src + rel);
        }
        CP_COMMIT();
    }

    // load A/B tiles (256 rows x 128B each, contiguous), swizzled
    {
        const char* srcA = (const char*)g_A + (size_t)i0 * 4096;
        const char* srcB = (const char*)g_B + (size_t)j0 * 4096;
        #pragma unroll
        for (int q = 0; q < 8; q++) {
            uint32_t rel = (uint32_t)(tid + q * 256) * 16u;
            uint32_t sw = SWZ(rel);
            *(uint4*)(sm + OFF_AS + sw) = *(const uint4*)(srcA + rel);
            *(uint4*)(sm + OFF_BS + sw) = *(const uint4*)(srcB + rel);
        }
    }
    __syncthreads();

    const int wm = wid >> 2, wn = wid & 3;
    const int lr = lane & 15;
    const int lc = (lane >> 4) << 4;
    const int mrow = lane >> 2;
    const int ncol = (lane & 3) * 2;

    float acc2[2][4][4];
    #pragma unroll
    for (int a = 0; a < 2; a++)
        #pragma unroll
        for (int b = 0; b < 4; b++)
            #pragma unroll
            for (int c = 0; c < 4; c++) acc2[a][b][c] = 0.f;

    int cidx = 0;
    for (int sl = 0; sl < 4; sl++) {
        // ---- GEMM1 slice: M=64 ((i,c_l)), N=256 ((j,d)), K=64 (s), fp32 acc ----
        const int mb = wm * 32, nb = wn * 64;
        float acc1[2][8][4];
        #pragma unroll
        for (int a = 0; a < 2; a++)
            #pragma unroll
            for (int b = 0; b < 8; b++)
                #pragma unroll
                for (int c = 0; c < 4; c++) acc1[a][b][c] = 0.f;

        #pragma unroll
        for (int k = 0; k < 4; k++) {
            uint32_t af[2][4];
            #pragma unroll
            for (int tm = 0; tm < 2; tm++) {
                int mm = mb + tm * 16 + lr;
                int r = ((mm >> 3) << 5) + sl * 8 + (mm & 7);
                ldsm4(af[tm], smb + OFF_AS + SWZ((uint32_t)(r * 128 + k * 32 + lc)));
            }
            uint32_t bf[8][2];
            #pragma unroll
            for (int tp = 0; tp < 4; tp++) {
                uint32_t q[4];
                int nn = nb + tp * 16 + lr;
                ldsm4(q, smb + OFF_BS + SWZ((uint32_t)(nn * 128 + k * 32 + lc)));
                bf[2*tp][0] = q[0]; bf[2*tp+1][0] = q[1];
                bf[2*tp][1] = q[2]; bf[2*tp+1][1] = q[3];
            }
            #pragma unroll
            for (int tm = 0; tm < 2; tm++)
                #pragma unroll
                for (int tn = 0; tn < 8; tn++)
                    mma16816(acc1[tm][tn], af[tm], bf[tn]);
        }
        __syncthreads();   // S1: all warps done reading Zs (prev sl chunk 3)

        // ---- remap Z -> Zs[ksub][pair][kk] fp16 ----
        #pragma unroll
        for (int tm = 0; tm < 2; tm++) {
            #pragma unroll
            for (int tn = 0; tn < 8; tn++) {
                int nn = nb + tn * 8 + ncol;
                int j = nn >> 5, d = nn & 31;
                #pragma unroll
                for (int h = 0; h < 2; h++) {
                    int mm = mb + tm * 16 + mrow + h * 8;
                    int i = mm >> 3, cl = mm & 7;
                    uint32_t rel = (uint32_t)((i * 8 + j) * 128 + ((cl & 1) * 32 + d) * 2);
                    __half2 hv = __floats2half2_rn(acc1[tm][tn][h*2], acc1[tm][tn][h*2+1]);
                    *(__half2*)(sm + OFF_ZS + (uint32_t)(cl >> 1) * 8192u + SWZ(rel)) = hv;
                }
            }
        }
        __syncthreads();   // S2: remap visible

        // ---- GEMM2: 4 chunks, one barrier per chunk ----
        const int pb = wm * 32, ob = wn * 32;
        for (int ksub = 0; ksub < 4; ksub++, cidx++) {
            CP_WAIT(0);        // W[cidx] landed (only outstanding group)
            __syncthreads();   // S3: visibility + all warps done with buf[(cidx-1)&1]

            // prefetch W[cidx+1] into the OTHER buffer
            if (cidx + 1 < 16) {
                const char* src = (const char*)g_W + (size_t)(cidx + 1) * 16384;
                uint32_t dst = smb + OFF_WO + (uint32_t)((cidx + 1) & 1) * 16384u;
                #pragma unroll
                for (int q = 0; q < 4; q++) {
                    uint32_t rel = (uint32_t)(tid + q * 256) * 16u;
                    CP16(dst + SWZ(rel), src + rel);
                }
                CP_COMMIT();
            }

            uint32_t zbase = smb + OFF_ZS + (uint32_t)ksub * 8192u;
            uint32_t wbase = smb + OFF_WO + (uint32_t)(cidx & 1) * 16384u;
            #pragma unroll
            for (int k = 0; k < 4; k++) {
                uint32_t af[2][4];
                #pragma unroll
                for (int tm = 0; tm < 2; tm++) {
                    int p = pb + tm * 16 + lr;
                    ldsm4(af[tm], zbase + SWZ((uint32_t)(p * 128 + k * 32 + lc)));
                }
                uint32_t bf[4][2];
                #pragma unroll
                for (int tp = 0; tp < 2; tp++) {
                    uint32_t q[4];
                    int o = ob + tp * 16 + lr;
                    ldsm4(q, wbase + SWZ((uint32_t)(o * 128 + k * 32 + lc)));
                    bf[2*tp][0] = q[0]; bf[2*tp+1][0] = q[1];
                    bf[2*tp][1] = q[2]; bf[2*tp+1][1] = q[3];
                }
                #pragma unroll
                for (int tm = 0; tm < 2; tm++)
                    #pragma unroll
                    for (int tn = 0; tn < 4; tn++)
                        mma16816(acc2[tm][tn], af[tm], bf[tn]);
            }
        }
    }

    // ---- epilogue: /denom, +bo, store ----
    const int pb = wm * 32, ob = wn * 32;
    float2 bo2[4];
    #pragma unroll
    for (int tn = 0; tn < 4; tn++)
        bo2[tn] = *(const float2*)(bo + ob + tn * 8 + ncol);

    #pragma unroll
    for (int tm = 0; tm < 2; tm++) {
        #pragma unroll
        for (int h = 0; h < 2; h++) {
            int pair = pb + tm * 16 + mrow + h * 8;
            int i = pair >> 3, j = pair & 7;
            float invd = sInvd[pair];
            float* op = out + ((size_t)(i0 + i) * N_DIM + (j0 + j)) * C_OUT;
            #pragma unroll
            for (int tn = 0; tn < 4; tn++) {
                float2 v;
                v.x = acc2[tm][tn][h*2]   * invd + bo2[tn].x;
                v.y = acc2[tm][tn][h*2+1] * invd + bo2[tn].y;
                *(float2*)(op + ob + tn * 8 + ncol) = v;
            }
        }
    }
}

// ---------------------------------------------------------------------------
extern "C" void kernel_launch(void* const* d_in, const int* in_sizes, int n_in,
                              void* d_out, int out_size)
{
    const float* m     = (const float*)d_in[0];
    const int*   mask  = (const int*)  d_in[1];
    const float* gamma = (const float*)d_in[2];
    const float* beta  = (const float*)d_in[3];
    const float* Wa    = (const float*)d_in[4];
    const float* Wb    = (const float*)d_in[5];
    const float* Wo    = (const float*)d_in[6];
    const float* bo    = (const float*)d_in[7];
    float* out = (float*)d_out;

    cudaFuncSetAttribute(main_kernel, cudaFuncAttributeMaxDynamicSharedMemorySize, SMEM_BYTES);

    prep_kernel<<<2 * N_DIM + C_OUT, 512>>>(m, mask, gamma, beta, Wa, Wb, Wo);

    dim3 grid(N_DIM / 8, N_DIM / 8);
    main_kernel<<<grid, 256, SMEM_BYTES>>>(bo, out);
}